// round 7
// baseline (speedup 1.0000x reference)
#include <cuda_runtime.h>
#include <stdint.h>

// ---- packed f32x2 helpers (sm_103a; only reachable via explicit PTX) ----
__device__ __forceinline__ unsigned long long pack2(float lo, float hi) {
    unsigned long long r;
    asm("mov.b64 %0, {%1, %2};" : "=l"(r) : "f"(lo), "f"(hi));
    return r;
}
__device__ __forceinline__ void unpack2(unsigned long long v, float& lo, float& hi) {
    asm("mov.b64 {%0, %1}, %2;" : "=f"(lo), "=f"(hi) : "l"(v));
}
__device__ __forceinline__ unsigned long long add2(unsigned long long a, unsigned long long b) {
    unsigned long long r;
    asm("add.rn.f32x2 %0, %1, %2;" : "=l"(r) : "l"(a), "l"(b));
    return r;
}
__device__ __forceinline__ unsigned long long mul2(unsigned long long a, unsigned long long b) {
    unsigned long long r;
    asm("mul.rn.f32x2 %0, %1, %2;" : "=l"(r) : "l"(a), "l"(b));
    return r;
}
__device__ __forceinline__ unsigned long long fma2(unsigned long long a, unsigned long long b,
                                                   unsigned long long c) {
    unsigned long long r;
    asm("fma.rn.f32x2 %0, %1, %2, %3;" : "=l"(r) : "l"(a), "l"(b), "l"(c));
    return r;
}

// Exact-equivalence notes (unchanged from R4, both protected):
//  * hash mask dropped: s <= ri+rj < 0.7, so d2 < s*s forces per-axis |d| < 1
//    -> voxel delta in {-1,0,1} -> the 27-neighborhood hash test is always true
//    for any pair that can be valid; collisions only touch pairs whose output
//    is 0 either way. Boolean-exact.
//  * fast-path filter: s*s < 0.49 always (radii in [0.05, 0.35)), so if every
//    d2 in a thread's 4 elements is >= 0.49, all 4 outputs are exactly 0.
//    The full reference predicate (j>i, ri<1, d2<s*s with reference op order)
//    runs only in the rare slow path (~0.6% of warp-rows).
#define ROWS 16
#define JPT  4   // j's per thread, strided by 256 for coalescing

__global__ __launch_bounds__(256)
void edge_kernel(const float* __restrict__ pts,
                 const float* __restrict__ rad,
                 const int* __restrict__ d_start,
                 float* __restrict__ out,
                 int n, int chunk) {
    const int tid = threadIdx.x;
    const int jbase = blockIdx.x * (256 * JPT);

    // ---- Tile setup (paid once per 16 rows): load 4 strided points straight
    // from pts/radii, negate, pack into f32x2 pairs. ----
    float pr[JPT];
    bool  jv[JPT];
    float nx[JPT], ny[JPT], nz[JPT];
#pragma unroll
    for (int k = 0; k < JPT; k++) {
        const int j = jbase + k * 256 + tid;
        jv[k] = (j < n);
        if (jv[k]) {
            nx[k] = -pts[3 * j + 0];
            ny[k] = -pts[3 * j + 1];
            nz[k] = -pts[3 * j + 2];
            pr[k] = rad[j];
        } else {
            nx[k] = -1e30f; ny[k] = -1e30f; nz[k] = -1e30f; pr[k] = 1e30f;
        }
    }
    unsigned long long npx[2], npy[2], npz[2];
#pragma unroll
    for (int p = 0; p < 2; p++) {
        npx[p] = pack2(nx[2 * p], nx[2 * p + 1]);
        npy[p] = pack2(ny[2 * p], ny[2 * p + 1]);
        npz[p] = pack2(nz[2 * p], nz[2 * p + 1]);
    }

    const int start = d_start[0];
    const int row0 = blockIdx.y * ROWS;
    float* op = out + (size_t)row0 * (size_t)n + (size_t)(jbase + tid);

#pragma unroll
    for (int r = 0; r < ROWS; r++, op += n) {
        const int row = row0 + r;
        if (row >= chunk) break;
        const int i = start + row;
        // Uniform broadcast loads (L1 hit after first warp).
        const float pix_s = pts[3 * i + 0];
        const float piy_s = pts[3 * i + 1];
        const float piz_s = pts[3 * i + 2];

        const unsigned long long pix = pack2(pix_s, pix_s);
        const unsigned long long piy = pack2(piy_s, piy_s);
        const unsigned long long piz = pack2(piz_s, piz_s);

        float d2s[JPT];
#pragma unroll
        for (int p = 0; p < 2; p++) {
            unsigned long long dx = add2(pix, npx[p]);   // pi - pj (exact: x + (-y))
            unsigned long long dy = add2(piy, npy[p]);
            unsigned long long dz = add2(piz, npz[p]);
            unsigned long long t  = mul2(dx, dx);
            t = fma2(dy, dy, t);
            t = fma2(dz, dz, t);
            unpack2(t, d2s[2 * p], d2s[2 * p + 1]);
        }

        const float mn = fminf(fminf(d2s[0], d2s[1]), fminf(d2s[2], d2s[3]));
        if (mn < 0.49f) {
            // Rare slow path: full reference predicate.
            const float ri = rad[i];
            const bool row_on = (ri < 1.0f);   // DIS_THRESHOLD
#pragma unroll
            for (int k = 0; k < JPT; k++) {
                const int j = jbase + k * 256 + tid;
                const float rj = pr[k];
                const float mr = 1.5f * fminf(ri, rj);
                const float s  = fminf(ri, mr) + fminf(rj, mr);
                const bool ok = row_on && (j > i) && (d2s[k] < s * s);
                if (jv[k]) op[k * 256] = ok ? d2s[k] : 0.0f;
            }
        } else {
            // Fast path: all 4 outputs are exactly zero.
#pragma unroll
            for (int k = 0; k < JPT; k++)
                if (jv[k]) op[k * 256] = 0.0f;
        }
    }
}

extern "C" void kernel_launch(void* const* d_in, const int* in_sizes, int n_in,
                              void* d_out, int out_size) {
    const float* pts   = (const float*)d_in[0];
    const float* rad   = (const float*)d_in[1];
    const int*   start = (const int*)d_in[2];
    float* out = (float*)d_out;

    const int n = in_sizes[0] / 3;           // number of points
    const int chunk = out_size / n;          // rows (end_idx - start_idx)

    dim3 grid((n + 256 * JPT - 1) / (256 * JPT), (chunk + ROWS - 1) / ROWS);
    edge_kernel<<<grid, 256>>>(pts, rad, start, out, n, chunk);
}

// round 9
// speedup vs baseline: 1.0530x; 1.0530x over previous
#include <cuda_runtime.h>
#include <stdint.h>

// ---- packed f32x2 helpers (sm_103a; only reachable via explicit PTX) ----
__device__ __forceinline__ unsigned long long pack2(float lo, float hi) {
    unsigned long long r;
    asm("mov.b64 %0, {%1, %2};" : "=l"(r) : "f"(lo), "f"(hi));
    return r;
}
__device__ __forceinline__ void unpack2(unsigned long long v, float& lo, float& hi) {
    asm("mov.b64 {%0, %1}, %2;" : "=f"(lo), "=f"(hi) : "l"(v));
}
__device__ __forceinline__ unsigned long long add2(unsigned long long a, unsigned long long b) {
    unsigned long long r;
    asm("add.rn.f32x2 %0, %1, %2;" : "=l"(r) : "l"(a), "l"(b));
    return r;
}
__device__ __forceinline__ unsigned long long mul2(unsigned long long a, unsigned long long b) {
    unsigned long long r;
    asm("mul.rn.f32x2 %0, %1, %2;" : "=l"(r) : "l"(a), "l"(b));
    return r;
}
__device__ __forceinline__ unsigned long long fma2(unsigned long long a, unsigned long long b,
                                                   unsigned long long c) {
    unsigned long long r;
    asm("fma.rn.f32x2 %0, %1, %2, %3;" : "=l"(r) : "l"(a), "l"(b), "l"(c));
    return r;
}

// Streaming (evict-first) 128-bit store: output is write-once, never re-read,
// and bigger than L2 -> keep it from thrashing the cache.
__device__ __forceinline__ void stg128_cs(float* p, float a, float b, float c, float d) {
    asm volatile("st.global.cs.v4.f32 [%0], {%1, %2, %3, %4};"
                 :: "l"(p), "f"(a), "f"(b), "f"(c), "f"(d) : "memory");
}

// Exact-equivalence notes (protected invariants from R4):
//  * hash mask dropped: s <= ri+rj < 0.7, so d2 < s*s forces per-axis |d| < 1
//    -> voxel delta in {-1,0,1} -> 27-neighborhood hash match is always true
//    for any pair that can be valid; collisions only affect pairs whose output
//    is 0 either way. Boolean-exact.
//  * fast-path filter: s*s < 0.49 always (radii in [0.05, 0.35)), so if every
//    d2 in a thread's 4 elements is >= 0.49, all 4 outputs are exactly 0.
//    The full reference predicate (j>i, ri<1, d2<s*s, reference op order) runs
//    only in the rare slow path.
#define ROWS 16
#define JPT  4   // contiguous j's per thread -> one STG.128 per row

__global__ __launch_bounds__(256)
void edge_kernel(const float* __restrict__ pts,
                 const float* __restrict__ rad,
                 const int* __restrict__ d_start,
                 float* __restrict__ out,
                 int n, int chunk) {
    const int tid = threadIdx.x;
    const int jbase = blockIdx.x * (256 * JPT);
    const int j0 = jbase + tid * JPT;          // this thread's 4 contiguous j's

    // ---- Tile setup (once per 16 rows): load 4 contiguous points, negate,
    // pack into f32x2 pairs. Strided lanes here are fine - amortized 16x. ----
    float pr[JPT];
    float nx[JPT], ny[JPT], nz[JPT];
    const bool full = (j0 + JPT <= n);
#pragma unroll
    for (int k = 0; k < JPT; k++) {
        const int j = j0 + k;
        if (j < n) {
            nx[k] = -pts[3 * j + 0];
            ny[k] = -pts[3 * j + 1];
            nz[k] = -pts[3 * j + 2];
            pr[k] = rad[j];
        } else {
            nx[k] = -1e30f; ny[k] = -1e30f; nz[k] = -1e30f; pr[k] = 1e30f;
        }
    }
    unsigned long long npx[2], npy[2], npz[2];
#pragma unroll
    for (int p = 0; p < 2; p++) {
        npx[p] = pack2(nx[2 * p], nx[2 * p + 1]);
        npy[p] = pack2(ny[2 * p], ny[2 * p + 1]);
        npz[p] = pack2(nz[2 * p], nz[2 * p + 1]);
    }

    const int start = d_start[0];
    const int row0 = blockIdx.y * ROWS;
    float* op = out + (size_t)row0 * (size_t)n + (size_t)j0;   // 16B-aligned

#pragma unroll
    for (int r = 0; r < ROWS; r++, op += n) {
        const int row = row0 + r;
        if (row >= chunk) break;
        const int i = start + row;
        // Uniform broadcast loads (L1 hit after first warp).
        const float pix_s = pts[3 * i + 0];
        const float piy_s = pts[3 * i + 1];
        const float piz_s = pts[3 * i + 2];

        const unsigned long long pix = pack2(pix_s, pix_s);
        const unsigned long long piy = pack2(piy_s, piy_s);
        const unsigned long long piz = pack2(piz_s, piz_s);

        float d2s[JPT];
#pragma unroll
        for (int p = 0; p < 2; p++) {
            unsigned long long dx = add2(pix, npx[p]);   // pi - pj (exact: x + (-y))
            unsigned long long dy = add2(piy, npy[p]);
            unsigned long long dz = add2(piz, npz[p]);
            unsigned long long t  = mul2(dx, dx);
            t = fma2(dy, dy, t);
            t = fma2(dz, dz, t);
            unpack2(t, d2s[2 * p], d2s[2 * p + 1]);
        }

        const float mn = fminf(fminf(d2s[0], d2s[1]), fminf(d2s[2], d2s[3]));
        if (mn >= 0.49f) {
            // Fast path: all 4 outputs exactly zero; one streaming STG.128.
            if (full) {
                stg128_cs(op, 0.0f, 0.0f, 0.0f, 0.0f);
            } else {
#pragma unroll
                for (int k = 0; k < JPT; k++)
                    if (j0 + k < n) op[k] = 0.0f;
            }
        } else {
            // Rare slow path: full reference predicate.
            const float ri = rad[i];
            const bool row_on = (ri < 1.0f);   // DIS_THRESHOLD
            float v[JPT];
#pragma unroll
            for (int k = 0; k < JPT; k++) {
                const int j = j0 + k;
                const float rj = pr[k];
                const float mr = 1.5f * fminf(ri, rj);
                const float s  = fminf(ri, mr) + fminf(rj, mr);
                const bool ok = row_on && (j > i) && (d2s[k] < s * s);
                v[k] = ok ? d2s[k] : 0.0f;
            }
            if (full) {
                stg128_cs(op, v[0], v[1], v[2], v[3]);
            } else {
#pragma unroll
                for (int k = 0; k < JPT; k++)
                    if (j0 + k < n) op[k] = v[k];
            }
        }
    }
}

extern "C" void kernel_launch(void* const* d_in, const int* in_sizes, int n_in,
                              void* d_out, int out_size) {
    const float* pts   = (const float*)d_in[0];
    const float* rad   = (const float*)d_in[1];
    const int*   start = (const int*)d_in[2];
    float* out = (float*)d_out;

    const int n = in_sizes[0] / 3;           // number of points
    const int chunk = out_size / n;          // rows (end_idx - start_idx)

    dim3 grid((n + 256 * JPT - 1) / (256 * JPT), (chunk + ROWS - 1) / ROWS);
    edge_kernel<<<grid, 256>>>(pts, rad, start, out, n, chunk);
}